// round 7
// baseline (speedup 1.0000x reference)
#include <cuda_runtime.h>
#include <cstdint>

#define BATCH   16
#define CHX     256
#define NPOS    170
#define TT      64
#define CIN     512
#define COUT    512
#define NHEAD   8
#define HDIM    64
#define BN      (BATCH*NPOS)      // 2720
#define TOKENS  (BN*TT)           // 174080
#define NTSTR   (NPOS*TT)         // 10880
#define QKV_ELEMS (BN*NHEAD*TT*HDIM)   // 89,128,960

// Stage geometry (words)
#define SA 136                    // A smem/gmem row stride (128 tokens + 8 pad)
#define SB 36                     // B smem/gmem row stride (32 k + 4 pad)
#define AW (32*SA)                // 4352 words  = 17408 B  (one A stage)
#define BW (128*SB)               // 4608 words  = 18432 B  (one B stage)
#define STAGE (AW+BW)             // 8960 words  = 35840 B
#define SMEM_BYTES (3*STAGE*4)    // 107520
#define STAGE_BYTES 35840

// Scratch (device globals). All tf32 bit patterns, pre-laid-out for bulk copies.
__device__ float g_x3[(size_t)1360*16*AW];   // [bnpair][kt][k32][tok136]  (378.8MB)
__device__ float g_w3[16*16*BW];             // [mat*4+nblk][kt][n128][k36] (4.7MB)
__device__ float g_q[QKV_ELEMS];             // [(bn*8+h)][t][dd]
__device__ float g_k[QKV_ELEMS];
__device__ float g_v[QKV_ELEMS];
__device__ float g_o3[(size_t)1360*16*AW];   // [tokblk][kt][k32][tok136]

// ---------------------------------------------------------------------------
__device__ __forceinline__ uint32_t f2tf32(float f) {
    uint32_t r;
    asm("cvt.rna.tf32.f32 %0, %1;" : "=r"(r) : "f"(f));
    return r;
}

__device__ __forceinline__ void mma_tf32(float* d, const uint32_t* a, const uint32_t* b) {
    asm volatile(
        "mma.sync.aligned.m16n8k8.row.col.f32.tf32.tf32.f32 "
        "{%0,%1,%2,%3},{%4,%5,%6,%7},{%8,%9},{%0,%1,%2,%3};\n"
        : "+f"(d[0]), "+f"(d[1]), "+f"(d[2]), "+f"(d[3])
        : "r"(a[0]), "r"(a[1]), "r"(a[2]), "r"(a[3]),
          "r"(b[0]), "r"(b[1]));
}

__device__ __forceinline__ uint32_t smem_u32(const void* p) {
    return (uint32_t)__cvta_generic_to_shared(p);
}
__device__ __forceinline__ void mbar_init(uint32_t a, uint32_t cnt) {
    asm volatile("mbarrier.init.shared.b64 [%0], %1;" :: "r"(a), "r"(cnt) : "memory");
}
__device__ __forceinline__ void mbar_expect(uint32_t a, uint32_t bytes) {
    asm volatile("mbarrier.arrive.expect_tx.shared.b64 _, [%0], %1;"
                 :: "r"(a), "r"(bytes) : "memory");
}
__device__ __forceinline__ void mbar_wait(uint32_t a, uint32_t parity) {
    asm volatile(
        "{\n\t.reg .pred P1;\n\t"
        "W_%=:\n\t"
        "mbarrier.try_wait.parity.acquire.cta.shared::cta.b64 P1, [%0], %1, 0x989680;\n\t"
        "@P1 bra D_%=;\n\t"
        "bra W_%=;\n\t"
        "D_%=:\n\t}"
        :: "r"(a), "r"(parity) : "memory");
}
__device__ __forceinline__ void bulk_g2s(uint32_t dst, const float* src,
                                         uint32_t bytes, uint32_t mbar) {
    asm volatile(
        "cp.async.bulk.shared::cluster.global.mbarrier::complete_tx::bytes "
        "[%0], [%1], %2, [%3];"
        :: "r"(dst), "l"(src), "r"(bytes), "r"(mbar) : "memory");
}

// ---------------------------------------------------------------------------
// Prepass 1: x||tem -> g_x3 (tf32, sigma-permuted tokens, bulk-stage layout).
// grid 8192 (= c*16 + b), block 256.
// ---------------------------------------------------------------------------
__global__ void cvt_x_kernel(const float* __restrict__ x, const float* __restrict__ tem)
{
    const int cb = blockIdx.x;
    const int c = cb >> 4, b = cb & 15;
    const float* src = (c < CHX) ? (x + (size_t)(b * CHX + c) * NTSTR)
                                 : (tem + (size_t)(b * CHX + c - CHX) * NTSTR);
    uint32_t* gx = (uint32_t*)g_x3;
    const int kt = c >> 5, kw = c & 31;

    for (int m = threadIdx.x; m < NTSTR / 4; m += 256) {
        int u = 4 * m;                       // stored position within row stream
        int blk = u & ~31, m8 = m & 7;
        uint4 o;
        o.x = f2tf32(__ldg(&src[blk + m8]));
        o.y = f2tf32(__ldg(&src[blk + m8 + 8]));
        o.z = f2tf32(__ldg(&src[blk + m8 + 16]));
        o.w = f2tf32(__ldg(&src[blk + m8 + 24]));
        size_t stage = (size_t)(b * 85 + (u >> 7)) * 16 + kt;
        *(uint4*)(gx + stage * AW + kw * SA + (u & 127)) = o;
    }
}

// ---------------------------------------------------------------------------
// Prepass 2: weights -> g_w3 tf32, rho-permuted k, padded bulk-stage layout.
// e = [mat 2b][nblk 2b][kt 4b][n 7b][r 5b] -> 1M threads, grid 4096 x 256.
// ---------------------------------------------------------------------------
__global__ void cvt_w_kernel(const float* __restrict__ Wq, const float* __restrict__ Wk,
                             const float* __restrict__ Wv, const float* __restrict__ Wo)
{
    int e = blockIdx.x * 256 + threadIdx.x;
    int mat  = e >> 18;
    int nblk = (e >> 16) & 3;
    int kt   = (e >> 12) & 15;
    int n    = (e >> 5) & 127;
    int r    = e & 31;
    int k    = kt * 32 + (r & 7) * 4 + (r >> 3);
    const float* W = (mat == 0) ? Wq : (mat == 1) ? Wk : (mat == 2) ? Wv : Wo;
    size_t dst = ((size_t)((mat * 4 + nblk) * 16 + kt) * 128 + n) * SB + r;
    ((uint32_t*)g_w3)[dst] = f2tf32(__ldg(&W[(nblk * 128 + n) * 512 + k]));
}

// ---------------------------------------------------------------------------
// Compute one 32-K tile (identical fragment math to R5; conflict-free banks).
// ---------------------------------------------------------------------------
__device__ __forceinline__ void mma_ktile(const float* As, const float* Bs,
                                          float (&acc)[2][8][4],
                                          int mbase, int nbase, int g, int t4)
{
#pragma unroll
    for (int h = 0; h < 2; h++) {
        uint4 a0 = *(const uint4*)(As + (h*16 + t4     ) * SA + mbase + 4*g);
        uint4 a1 = *(const uint4*)(As + (h*16 + t4 + 4 ) * SA + mbase + 4*g);
        uint4 a2 = *(const uint4*)(As + (h*16 + t4 + 8 ) * SA + mbase + 4*g);
        uint4 a3 = *(const uint4*)(As + (h*16 + t4 + 12) * SA + mbase + 4*g);
        uint32_t af0[2][4] = {{a0.x, a0.y, a1.x, a1.y}, {a0.z, a0.w, a1.z, a1.w}};
        uint32_t af1[2][4] = {{a2.x, a2.y, a3.x, a3.y}, {a2.z, a2.w, a3.z, a3.w}};
#pragma unroll
        for (int ni = 0; ni < 8; ni++) {
            int c = nbase + ni * 8 + g;
            uint4 bv = *(const uint4*)(Bs + c * SB + t4 * 8 + h * 4);
            uint32_t bf0[2] = {bv.x, bv.y};
            uint32_t bf1[2] = {bv.z, bv.w};
            mma_tf32(acc[0][ni], af0[0], bf0);
            mma_tf32(acc[1][ni], af0[1], bf0);
            mma_tf32(acc[0][ni], af1[0], bf1);
            mma_tf32(acc[1][ni], af1[1], bf1);
        }
    }
}

// ---------------------------------------------------------------------------
// Shared bulk-pipeline GEMM body. aSrc/bSrc point at stage 0 (kt advances by
// AW / BW words per stage). 3 stages, mbarrier complete_tx, 2 bulks per stage.
// ---------------------------------------------------------------------------
__device__ __forceinline__ void gemm_pipeline(const float* aSrc, const float* bSrc,
                                              float* sm, const uint64_t* mbars,
                                              float (&acc)[2][8][4],
                                              int tid, int mbase, int nbase,
                                              int g, int t4)
{
    uint32_t mb0 = smem_u32(mbars);
    uint32_t smb = smem_u32(sm);

    if (tid == 0) {
#pragma unroll
        for (int s = 0; s < 3; s++) mbar_init(mb0 + s * 8, 1);
    }
    __syncthreads();

    if (tid == 0) {
#pragma unroll
        for (int s = 0; s < 3; s++) {
            mbar_expect(mb0 + s * 8, STAGE_BYTES);
            bulk_g2s(smb + s * STAGE * 4,          aSrc + (size_t)s * AW, AW * 4, mb0 + s * 8);
            bulk_g2s(smb + s * STAGE * 4 + AW * 4, bSrc + (size_t)s * BW, BW * 4, mb0 + s * 8);
        }
    }

    for (int it = 0; it < 16; it++) {
        const int buf = it % 3;
        mbar_wait(mb0 + buf * 8, (it / 3) & 1);
        const float* As = sm + buf * STAGE;
        const float* Bs = As + AW;
        mma_ktile(As, Bs, acc, mbase, nbase, g, t4);
        __syncthreads();
        int nx = it + 3;
        if (nx < 16 && tid == 0) {
            mbar_expect(mb0 + buf * 8, STAGE_BYTES);
            bulk_g2s(smb + buf * STAGE * 4,          aSrc + (size_t)nx * AW, AW * 4, mb0 + buf * 8);
            bulk_g2s(smb + buf * STAGE * 4 + AW * 4, bSrc + (size_t)nx * BW, BW * 4, mb0 + buf * 8);
        }
    }
}

// ---------------------------------------------------------------------------
// Kernel 1: QKV projection. grid (12, 1360): x = variant, y = bn-pair.
// ---------------------------------------------------------------------------
__global__ __launch_bounds__(256, 2)
void qkv_kernel(const float* __restrict__ bq, const float* __restrict__ bk,
                const float* __restrict__ bv)
{
    extern __shared__ float sm[];
    __shared__ __align__(8) uint64_t mbars[3];

    const int tid = threadIdx.x;
    const int bn0 = blockIdx.y * 2;
    const int y   = blockIdx.x;
    const int mat = y >> 2;             // 0:q 1:k 2:v
    const int r0  = (y & 3) * 128;

    const float* bias;  float* outBuf;
    if (mat == 0)      { bias = bq; outBuf = g_q; }
    else if (mat == 1) { bias = bk; outBuf = g_k; }
    else               { bias = bv; outBuf = g_v; }

    const int lane = tid & 31, wid = tid >> 5;
    const int wm = wid & 3, wn = wid >> 2;
    const int g = lane >> 2, t4 = lane & 3;
    const int mbase = wm * 32, nbase = wn * 64;

    float acc[2][8][4];
#pragma unroll
    for (int mi = 0; mi < 2; mi++)
#pragma unroll
        for (int ni = 0; ni < 8; ni++)
#pragma unroll
            for (int j = 0; j < 4; j++) acc[mi][ni][j] = 0.f;

    const float* aSrc = g_x3 + (size_t)blockIdx.y * 16 * AW;
    const float* bSrc = g_w3 + (size_t)(mat * 4 + (y & 3)) * 16 * BW;

    gemm_pipeline(aSrc, bSrc, sm, mbars, acc, tid, mbase, nbase, g, t4);

    // Epilogue: bias + store tf32 bits into per-head [T,d] tiles
    uint32_t* ob32 = (uint32_t*)outBuf;
#pragma unroll
    for (int mi = 0; mi < 2; mi++) {
        int rloc = mbase + mi * 16 + g;          // acc rows == original tokens
        int bn = bn0 + (rloc >> 6);
        int t  = rloc & 63;
        int tileBase = (bn * NHEAD) * (TT * HDIM);
#pragma unroll
        for (int ni = 0; ni < 8; ni++) {
            int jj = nbase + ni * 8 + 2 * t4;
            int o = r0 + jj;
            int h = o >> 6, dd = o & 63;
            float b0 = bias[o], b1 = bias[o + 1];
            uint2 v0 = make_uint2(f2tf32(acc[mi][ni][0] + b0), f2tf32(acc[mi][ni][1] + b1));
            uint2 v1 = make_uint2(f2tf32(acc[mi][ni][2] + b0), f2tf32(acc[mi][ni][3] + b1));
            int base = tileBase + h * (TT * HDIM) + dd;
            *(uint2*)&ob32[base + t * HDIM]       = v0;
            *(uint2*)&ob32[base + (t + 8) * HDIM] = v1;
        }
    }
}

// ---------------------------------------------------------------------------
// Kernel 2: causal attention per (bn, head) tile. Inputs tf32 bits.
// Epilogue writes O^T into g_o3's bulk-stage layout.
// ---------------------------------------------------------------------------
__global__ __launch_bounds__(128, 4)
void attn_kernel()
{
    __shared__ uint32_t Qs[64 * 68];   // Q, then P
    __shared__ uint32_t Ks[64 * 68];   // K, then V^T, then O^T

    const int tid = threadIdx.x;
    const int lane = tid & 31, wid = tid >> 5;
    const int g = lane >> 2, t4 = lane & 3;
    const int bh = blockIdx.x;
    const int base = bh * (TT * HDIM);

    const uint32_t* gq = (const uint32_t*)g_q;
    const uint32_t* gk = (const uint32_t*)g_k;
    const uint32_t* gv = (const uint32_t*)g_v;

#pragma unroll
    for (int i = tid * 4; i < TT * HDIM; i += 512) {
        int t = i >> 6, d = i & 63;
        *(uint4*)&Qs[t * 68 + d] = *(const uint4*)(gq + base + i);
        *(uint4*)&Ks[t * 68 + d] = *(const uint4*)(gk + base + i);
    }
    __syncthreads();

    const int rbase = wid * 16;
    float s[8][4];
#pragma unroll
    for (int ni = 0; ni < 8; ni++)
#pragma unroll
        for (int j = 0; j < 4; j++) s[ni][j] = 0.f;

#pragma unroll
    for (int ks = 0; ks < 64; ks += 8) {
        uint32_t af[4];
        int r = rbase + g;
        af[0] = Qs[r * 68 + ks + t4];
        af[1] = Qs[(r + 8) * 68 + ks + t4];
        af[2] = Qs[r * 68 + ks + t4 + 4];
        af[3] = Qs[(r + 8) * 68 + ks + t4 + 4];
#pragma unroll
        for (int ni = 0; ni < 8; ni++) {
            uint32_t bf[2];
            bf[0] = Ks[(ni * 8 + g) * 68 + ks + t4];
            bf[1] = Ks[(ni * 8 + g) * 68 + ks + t4 + 4];
            mma_tf32(s[ni], af, bf);
        }
    }
    __syncthreads();

    const int rA = rbase + g, rB = rA + 8;
    float mx0 = -1e30f, mx1 = -1e30f;
#pragma unroll
    for (int ni = 0; ni < 8; ni++) {
        int c0 = ni * 8 + 2 * t4, c1 = c0 + 1;
        s[ni][0] = (c0 <= rA) ? s[ni][0] * 0.125f : -32767.0f;
        s[ni][1] = (c1 <= rA) ? s[ni][1] * 0.125f : -32767.0f;
        s[ni][2] = (c0 <= rB) ? s[ni][2] * 0.125f : -32767.0f;
        s[ni][3] = (c1 <= rB) ? s[ni][3] * 0.125f : -32767.0f;
        mx0 = fmaxf(mx0, fmaxf(s[ni][0], s[ni][1]));
        mx1 = fmaxf(mx1, fmaxf(s[ni][2], s[ni][3]));
    }
    mx0 = fmaxf(mx0, __shfl_xor_sync(0xffffffffu, mx0, 1));
    mx0 = fmaxf(mx0, __shfl_xor_sync(0xffffffffu, mx0, 2));
    mx1 = fmaxf(mx1, __shfl_xor_sync(0xffffffffu, mx1, 1));
    mx1 = fmaxf(mx1, __shfl_xor_sync(0xffffffffu, mx1, 2));

    float sm0 = 0.f, sm1 = 0.f;
#pragma unroll
    for (int ni = 0; ni < 8; ni++) {
        s[ni][0] = __expf(s[ni][0] - mx0); sm0 += s[ni][0];
        s[ni][1] = __expf(s[ni][1] - mx0); sm0 += s[ni][1];
        s[ni][2] = __expf(s[ni][2] - mx1); sm1 += s[ni][2];
        s[ni][3] = __expf(s[ni][3] - mx1); sm1 += s[ni][3];
    }
    sm0 += __shfl_xor_sync(0xffffffffu, sm0, 1);
    sm0 += __shfl_xor_sync(0xffffffffu, sm0, 2);
    sm1 += __shfl_xor_sync(0xffffffffu, sm1, 1);
    sm1 += __shfl_xor_sync(0xffffffffu, sm1, 2);
    float inv0 = 1.f / sm0, inv1 = 1.f / sm1;

#pragma unroll
    for (int ni = 0; ni < 8; ni++) {
        int c0 = ni * 8 + 2 * t4;
        Qs[rA * 68 + c0]     = f2tf32(s[ni][0] * inv0);
        Qs[rA * 68 + c0 + 1] = f2tf32(s[ni][1] * inv0);
        Qs[rB * 68 + c0]     = f2tf32(s[ni][2] * inv1);
        Qs[rB * 68 + c0 + 1] = f2tf32(s[ni][3] * inv1);
    }
    // V^T -> Ks
#pragma unroll
    for (int i = tid * 4; i < TT * HDIM; i += 512) {
        int t = i >> 6, d = i & 63;
        uint4 v4 = *(const uint4*)(gv + base + i);
        Ks[(d + 0) * 68 + t] = v4.x;
        Ks[(d + 1) * 68 + t] = v4.y;
        Ks[(d + 2) * 68 + t] = v4.z;
        Ks[(d + 3) * 68 + t] = v4.w;
    }
    __syncthreads();

    float o[8][4];
#pragma unroll
    for (int ni = 0; ni < 8; ni++)
#pragma unroll
        for (int j = 0; j < 4; j++) o[ni][j] = 0.f;

#pragma unroll
    for (int ks = 0; ks < 64; ks += 8) {
        uint32_t af[4];
        int r = rbase + g;
        af[0] = Qs[r * 68 + ks + t4];
        af[1] = Qs[(r + 8) * 68 + ks + t4];
        af[2] = Qs[r * 68 + ks + t4 + 4];
        af[3] = Qs[(r + 8) * 68 + ks + t4 + 4];
#pragma unroll
        for (int ni = 0; ni < 8; ni++) {
            uint32_t bf[2];
            bf[0] = Ks[(ni * 8 + g) * 68 + ks + t4];
            bf[1] = Ks[(ni * 8 + g) * 68 + ks + t4 + 4];
            mma_tf32(o[ni], af, bf);
        }
    }
    __syncthreads();    // everyone done reading Ks

    // O^T (tf32) -> Ks[dd][t]
#pragma unroll
    for (int ni = 0; ni < 8; ni++) {
        int dd = ni * 8 + 2 * t4;
        Ks[(dd + 0) * 68 + rA] = f2tf32(o[ni][0]);
        Ks[(dd + 1) * 68 + rA] = f2tf32(o[ni][1]);
        Ks[(dd + 0) * 68 + rB] = f2tf32(o[ni][2]);
        Ks[(dd + 1) * 68 + rB] = f2tf32(o[ni][3]);
    }
    __syncthreads();

    // Dump to g_o3 bulk layout: [tokblk][kt][kw 0..31][tok136], sigma-stored.
    const int bn = bh >> 3, h = bh & 7;
    uint32_t* go3 = (uint32_t*)g_o3;
    const int chunk = tid & 15;
    const int hi = (chunk >> 3) * 32, m8 = chunk & 7;
    const size_t tb = (size_t)(bn >> 1) * 16;
    const int toff = (bn & 1) * 64 + chunk * 4;
#pragma unroll
    for (int p = 0; p < 8; p++) {
        int row = (tid >> 4) + p * 8;     // dd 0..63
        int kt = h * 2 + (row >> 5), kw = row & 31;
        uint4 w;
        w.x = Ks[row * 68 + hi + m8];
        w.y = Ks[row * 68 + hi + m8 + 8];
        w.z = Ks[row * 68 + hi + m8 + 16];
        w.w = Ks[row * 68 + hi + m8 + 24];
        *(uint4*)(go3 + (tb + kt) * AW + kw * SA + toff) = w;
    }
}

// ---------------------------------------------------------------------------
// Kernel 3: output projection + bias + ReLU. grid (4, 1360): x = n-block.
// ---------------------------------------------------------------------------
__global__ __launch_bounds__(256, 2)
void out_kernel(const float* __restrict__ bo, float* __restrict__ out)
{
    extern __shared__ float sm[];
    __shared__ __align__(8) uint64_t mbars[3];
    __shared__ int outOff[128];

    const int tid = threadIdx.x;
    const int m0  = blockIdx.y * 128;
    const int r0  = blockIdx.x * 128;

    if (tid < 128) {
        int token = m0 + tid;
        int bn = token >> 6;
        int b = bn / NPOS, n = bn % NPOS;
        outOff[tid] = (b * COUT * NPOS + n) * TT + (token & 63);
    }

    const int lane = tid & 31, wid = tid >> 5;
    const int wm = wid & 3, wn = wid >> 2;
    const int g = lane >> 2, t4 = lane & 3;
    const int mbase = wm * 32, nbase = wn * 64;

    float acc[2][8][4];
#pragma unroll
    for (int mi = 0; mi < 2; mi++)
#pragma unroll
        for (int ni = 0; ni < 8; ni++)
#pragma unroll
            for (int j = 0; j < 4; j++) acc[mi][ni][j] = 0.f;

    const float* aSrc = g_o3 + (size_t)blockIdx.y * 16 * AW;
    const float* bSrc = g_w3 + (size_t)(12 + blockIdx.x) * 16 * BW;

    gemm_pipeline(aSrc, bSrc, sm, mbars, acc, tid, mbase, nbase, g, t4);

#pragma unroll
    for (int mi = 0; mi < 2; mi++) {
        int rloc = mbase + mi * 16 + g;
        int off0 = outOff[rloc];
        int off1 = outOff[rloc + 8];
#pragma unroll
        for (int ni = 0; ni < 8; ni++) {
            int jj = nbase + ni * 8 + 2 * t4;
            int o = r0 + jj;
            float b0 = bo[o], b1 = bo[o + 1];
            out[off0 + o * NTSTR]       = fmaxf(acc[mi][ni][0] + b0, 0.f);
            out[off0 + (o + 1) * NTSTR] = fmaxf(acc[mi][ni][1] + b1, 0.f);
            out[off1 + o * NTSTR]       = fmaxf(acc[mi][ni][2] + b0, 0.f);
            out[off1 + (o + 1) * NTSTR] = fmaxf(acc[mi][ni][3] + b1, 0.f);
        }
    }
}

// ---------------------------------------------------------------------------
extern "C" void kernel_launch(void* const* d_in, const int* in_sizes, int n_in,
                              void* d_out, int out_size)
{
    const float* x   = (const float*)d_in[0];
    const float* tem = (const float*)d_in[1];
    const float* Wq  = (const float*)d_in[2];
    const float* bq  = (const float*)d_in[3];
    const float* Wk  = (const float*)d_in[4];
    const float* bk  = (const float*)d_in[5];
    const float* Wv  = (const float*)d_in[6];
    const float* bv  = (const float*)d_in[7];
    const float* Wo  = (const float*)d_in[8];
    const float* bo  = (const float*)d_in[9];
    float* out = (float*)d_out;

    cudaFuncSetAttribute(qkv_kernel, cudaFuncAttributeMaxDynamicSharedMemorySize, SMEM_BYTES);
    cudaFuncSetAttribute(out_kernel, cudaFuncAttributeMaxDynamicSharedMemorySize, SMEM_BYTES);

    cvt_x_kernel<<<512 * 16, 256>>>(x, tem);
    cvt_w_kernel<<<4096, 256>>>(Wq, Wk, Wv, Wo);

    dim3 g1(12, BN / 2);
    qkv_kernel<<<g1, 256, SMEM_BYTES>>>(bq, bk, bv);

    attn_kernel<<<BN * NHEAD, 128>>>();

    dim3 g3(4, BN / 2);
    out_kernel<<<g3, 256, SMEM_BYTES>>>(bo, out);
}

// round 9
// speedup vs baseline: 1.2251x; 1.2251x over previous
#include <cuda_runtime.h>
#include <cstdint>

#define BATCH   16
#define CHX     256
#define NPOS    170
#define TT      64
#define CIN     512
#define COUT    512
#define NHEAD   8
#define HDIM    64
#define BN      (BATCH*NPOS)      // 2720
#define TOKENS  (BN*TT)           // 174080
#define NTSTR   (NPOS*TT)         // 10880
#define QKV_ELEMS (BN*NHEAD*TT*HDIM)   // 89,128,960

// Scratch (device globals — no allocation allowed). All hold tf32 bit patterns.
__device__ float g_x[CIN*TOKENS];      // [c][token, sigma-permuted per 32-block]
__device__ float g_w[4*512*512];       // [mat(q,k,v,o)][n][ktile][rho-permuted k]
__device__ float g_q[QKV_ELEMS];       // [(bn*8+h)][t][dd]
__device__ float g_k[QKV_ELEMS];
__device__ float g_v[QKV_ELEMS];
__device__ float g_o2[CIN*TOKENS];     // [c][token, sigma-permuted]  (attention out)

// ---------------------------------------------------------------------------
__device__ __forceinline__ uint32_t f2tf32(float f) {
    uint32_t r;
    asm("cvt.rna.tf32.f32 %0, %1;" : "=r"(r) : "f"(f));
    return r;
}

__device__ __forceinline__ void mma_tf32(float* d, const uint32_t* a, const uint32_t* b) {
    asm volatile(
        "mma.sync.aligned.m16n8k8.row.col.f32.tf32.tf32.f32 "
        "{%0,%1,%2,%3},{%4,%5,%6,%7},{%8,%9},{%0,%1,%2,%3};\n"
        : "+f"(d[0]), "+f"(d[1]), "+f"(d[2]), "+f"(d[3])
        : "r"(a[0]), "r"(a[1]), "r"(a[2]), "r"(a[3]),
          "r"(b[0]), "r"(b[1]));
}

__device__ __forceinline__ void cpasync16(float* smem_dst, const float* gsrc) {
    uint32_t s = (uint32_t)__cvta_generic_to_shared(smem_dst);
    asm volatile("cp.async.cg.shared.global [%0], [%1], 16;\n"
                 :: "r"(s), "l"(gsrc) : "memory");
}
#define CP_COMMIT() asm volatile("cp.async.commit_group;\n" ::: "memory")
#define CP_WAIT2()  asm volatile("cp.async.wait_group 2;\n" ::: "memory")

// ---------------------------------------------------------------------------
// Prepass 1: x||tem -> g_x (tf32, sigma-permuted tokens).
// sigma(t) = (t&7)*4 + (t>>3) within each 32-token block.
// ---------------------------------------------------------------------------
__global__ void cvt_x_kernel(const float* __restrict__ x, const float* __restrict__ tem)
{
    const int cb = blockIdx.x;
    const int c = cb >> 4, b = cb & 15;
    const float* src = (c < CHX) ? (x + (size_t)(b * CHX + c) * NTSTR)
                                 : (tem + (size_t)(b * CHX + c - CHX) * NTSTR);
    uint32_t* dst = (uint32_t*)g_x + (size_t)c * TOKENS + b * NTSTR;

    for (int m = threadIdx.x; m < NTSTR / 4; m += 256) {
        int u = 4 * m;
        int blk = u & ~31, m8 = m & 7;
        uint4 o;
        o.x = f2tf32(__ldg(&src[blk + m8]));
        o.y = f2tf32(__ldg(&src[blk + m8 + 8]));
        o.z = f2tf32(__ldg(&src[blk + m8 + 16]));
        o.w = f2tf32(__ldg(&src[blk + m8 + 24]));
        *(uint4*)(dst + u) = o;
    }
}

// ---------------------------------------------------------------------------
// Prepass 2: weights -> g_w tf32, k rho-permuted per 32-k tile.
// stored[r] holds original k = kt*32 + (r&7)*4 + (r>>3). 1M elems, grid 4096.
// ---------------------------------------------------------------------------
__global__ void cvt_w_kernel(const float* __restrict__ Wq, const float* __restrict__ Wk,
                             const float* __restrict__ Wv, const float* __restrict__ Wo)
{
    int e = blockIdx.x * 256 + threadIdx.x;          // 0 .. 1M-1
    int mat = e >> 18;
    int rem = e & ((1 << 18) - 1);
    int n  = rem >> 9;
    int kt = (rem >> 5) & 15;
    int r  = rem & 31;
    int k  = kt * 32 + (r & 7) * 4 + (r >> 3);
    const float* W = (mat == 0) ? Wq : (mat == 1) ? Wk : (mat == 2) ? Wv : Wo;
    ((uint32_t*)g_w)[e] = f2tf32(__ldg(&W[n * 512 + k]));
}

// ---------------------------------------------------------------------------
// GEMM tile geometry: A [32 k][128 tok-sigma] stride 136, B [128 n][32 k-rho]
// stride 36. All tf32 bits.
// mma_ktile R7: B fragments for all 8 ni loaded up-front; MMAs run in two
// passes of 16 all-distinct accumulators -> RAW reuse distance 16 (was 2 in
// R5/R6 -- the dependency stall that caused both regressions).
// Per-acc accumulation order (octet A then octet B) unchanged -> bit-identical.
// ---------------------------------------------------------------------------
#define SA 136
#define SB 36
#define AW (32*SA)            // 4352 words
#define BW (128*SB)           // 4608 words
#define STAGE (AW+BW)         // 8960 words
#define SMEM_BYTES (3*STAGE*4)   // 107520

__device__ __forceinline__ void mma_ktile(const float* As, const float* Bs,
                                          float (&acc)[2][8][4],
                                          int mbase, int nbase, int g, int t4)
{
#pragma unroll
    for (int h = 0; h < 2; h++) {
        uint4 a0 = *(const uint4*)(As + (h*16 + t4     ) * SA + mbase + 4*g);
        uint4 a1 = *(const uint4*)(As + (h*16 + t4 + 4 ) * SA + mbase + 4*g);
        uint4 a2 = *(const uint4*)(As + (h*16 + t4 + 8 ) * SA + mbase + 4*g);
        uint4 a3 = *(const uint4*)(As + (h*16 + t4 + 12) * SA + mbase + 4*g);
        uint32_t af0[2][4] = {{a0.x, a0.y, a1.x, a1.y}, {a0.z, a0.w, a1.z, a1.w}};
        uint32_t af1[2][4] = {{a2.x, a2.y, a3.x, a3.y}, {a2.z, a2.w, a3.z, a3.w}};

        uint4 bv[8];
#pragma unroll
        for (int ni = 0; ni < 8; ni++)
            bv[ni] = *(const uint4*)(Bs + (nbase + ni * 8 + g) * SB + t4 * 8 + h * 4);

        // pass 1: octet A into all 16 accumulators (all distinct)
#pragma unroll
        for (int ni = 0; ni < 8; ni++) {
            uint32_t bf0[2] = {bv[ni].x, bv[ni].y};
            mma_tf32(acc[0][ni], af0[0], bf0);
            mma_tf32(acc[1][ni], af0[1], bf0);
        }
        // pass 2: octet B into all 16 accumulators (reuse distance = 16)
#pragma unroll
        for (int ni = 0; ni < 8; ni++) {
            uint32_t bf1[2] = {bv[ni].z, bv[ni].w};
            mma_tf32(acc[0][ni], af1[0], bf1);
            mma_tf32(acc[1][ni], af1[1], bf1);
        }
    }
}

// ---------------------------------------------------------------------------
// Kernel 1: QKV projection. grid (12, 1360): x = variant (L2 reuse of A).
// ---------------------------------------------------------------------------
__global__ __launch_bounds__(256, 2)
void qkv_kernel(const float* __restrict__ bq, const float* __restrict__ bk,
                const float* __restrict__ bv)
{
    extern __shared__ float sm[];

    const int tid = threadIdx.x;
    const int bn0 = blockIdx.y * 2;
    const int y   = blockIdx.x;
    const int mat = y >> 2;             // 0:q 1:k 2:v
    const int r0  = (y & 3) * 128;

    const float* bias;  float* outBuf;
    if (mat == 0)      { bias = bq; outBuf = g_q; }
    else if (mat == 1) { bias = bk; outBuf = g_k; }
    else               { bias = bv; outBuf = g_v; }

    // cp.async chunk metadata
    int kA[4], tcA[4], dstA[4], gB[4], dstB[4];
#pragma unroll
    for (int j = 0; j < 4; j++) {
        int cidx = tid + j * 256;
        kA[j]  = cidx >> 5;
        int tc = cidx & 31;
        tcA[j] = bn0 * 64 + tc * 4;
        dstA[j] = kA[j] * SA + tc * 4;
        int nn = cidx >> 3, kc = cidx & 7;
        gB[j]   = ((mat * 512 + r0 + nn) * 16) * 32 + kc * 4;   // + kt*32 later
        dstB[j] = nn * SB + kc * 4;
    }

    const int lane = tid & 31, wid = tid >> 5;
    const int wm = wid & 3, wn = wid >> 2;
    const int g = lane >> 2, t4 = lane & 3;
    const int mbase = wm * 32, nbase = wn * 64;

    float acc[2][8][4];
#pragma unroll
    for (int mi = 0; mi < 2; mi++)
#pragma unroll
        for (int ni = 0; ni < 8; ni++)
#pragma unroll
            for (int j = 0; j < 4; j++) acc[mi][ni][j] = 0.f;

    auto issue = [&](int stage, int kt) {
        float* As = sm + stage * STAGE;
        float* Bs = As + AW;
#pragma unroll
        for (int j = 0; j < 4; j++)
            cpasync16(As + dstA[j], g_x + (kt * 32 + kA[j]) * TOKENS + tcA[j]);
#pragma unroll
        for (int j = 0; j < 4; j++)
            cpasync16(Bs + dstB[j], g_w + gB[j] + kt * 32);
    };

#pragma unroll
    for (int s = 0; s < 3; s++) { issue(s, s); CP_COMMIT(); }

    for (int it = 0; it < 16; it++) {
        CP_WAIT2();
        __syncthreads();
        const int buf = it % 3;
        const float* As = sm + buf * STAGE;
        const float* Bs = As + AW;
        mma_ktile(As, Bs, acc, mbase, nbase, g, t4);
        __syncthreads();
        int nx = it + 3;
        if (nx < 16) issue(buf, nx);
        CP_COMMIT();
    }

    // Epilogue: bias + store tf32 bits into per-head [T,d] tiles
    uint32_t* ob32 = (uint32_t*)outBuf;
#pragma unroll
    for (int mi = 0; mi < 2; mi++) {
        int rloc = mbase + mi * 16 + g;          // acc rows == original tokens
        int bn = bn0 + (rloc >> 6);
        int t  = rloc & 63;
        int tileBase = (bn * NHEAD) * (TT * HDIM);
#pragma unroll
        for (int ni = 0; ni < 8; ni++) {
            int jj = nbase + ni * 8 + 2 * t4;
            int o = r0 + jj;
            int h = o >> 6, dd = o & 63;
            float b0 = bias[o], b1 = bias[o + 1];
            uint2 v0 = make_uint2(f2tf32(acc[mi][ni][0] + b0), f2tf32(acc[mi][ni][1] + b1));
            uint2 v1 = make_uint2(f2tf32(acc[mi][ni][2] + b0), f2tf32(acc[mi][ni][3] + b1));
            int base = tileBase + h * (TT * HDIM) + dd;
            *(uint2*)&ob32[base + t * HDIM]       = v0;
            *(uint2*)&ob32[base + (t + 8) * HDIM] = v1;
        }
    }
}

// ---------------------------------------------------------------------------
// Kernel 2: causal attention per (bn, head) tile. Inputs already tf32 bits.
// Epilogue transposes O into g_o2 [c][token-sigma] (tf32 bits).
// ---------------------------------------------------------------------------
__global__ __launch_bounds__(128, 4)
void attn_kernel()
{
    __shared__ uint32_t Qs[64 * 68];   // Q, then P
    __shared__ uint32_t Ks[64 * 68];   // K, then V^T, then O^T

    const int tid = threadIdx.x;
    const int lane = tid & 31, wid = tid >> 5;
    const int g = lane >> 2, t4 = lane & 3;
    const int bh = blockIdx.x;
    const int base = bh * (TT * HDIM);

    const uint32_t* gq = (const uint32_t*)g_q;
    const uint32_t* gk = (const uint32_t*)g_k;
    const uint32_t* gv = (const uint32_t*)g_v;

#pragma unroll
    for (int i = tid * 4; i < TT * HDIM; i += 512) {
        int t = i >> 6, d = i & 63;
        *(uint4*)&Qs[t * 68 + d] = *(const uint4*)(gq + base + i);
        *(uint4*)&Ks[t * 68 + d] = *(const uint4*)(gk + base + i);
    }
    __syncthreads();

    const int rbase = wid * 16;
    float s[8][4];
#pragma unroll
    for (int ni = 0; ni < 8; ni++)
#pragma unroll
        for (int j = 0; j < 4; j++) s[ni][j] = 0.f;

#pragma unroll
    for (int ks = 0; ks < 64; ks += 8) {
        uint32_t af[4];
        int r = rbase + g;
        af[0] = Qs[r * 68 + ks + t4];
        af[1] = Qs[(r + 8) * 68 + ks + t4];
        af[2] = Qs[r * 68 + ks + t4 + 4];
        af[3] = Qs[(r + 8) * 68 + ks + t4 + 4];
#pragma unroll
        for (int ni = 0; ni < 8; ni++) {
            uint32_t bf[2];
            bf[0] = Ks[(ni * 8 + g) * 68 + ks + t4];
            bf[1] = Ks[(ni * 8 + g) * 68 + ks + t4 + 4];
            mma_tf32(s[ni], af, bf);
        }
    }
    __syncthreads();

    const int rA = rbase + g, rB = rA + 8;
    float mx0 = -1e30f, mx1 = -1e30f;
#pragma unroll
    for (int ni = 0; ni < 8; ni++) {
        int c0 = ni * 8 + 2 * t4, c1 = c0 + 1;
        s[ni][0] = (c0 <= rA) ? s[ni][0] * 0.125f : -32767.0f;
        s[ni][1] = (c1 <= rA) ? s[ni][1] * 0.125f : -32767.0f;
        s[ni][2] = (c0 <= rB) ? s[ni][2] * 0.125f : -32767.0f;
        s[ni][3] = (c1 <= rB) ? s[ni][3] * 0.125f : -32767.0f;
        mx0 = fmaxf(mx0, fmaxf(s[ni][0], s[ni][1]));
        mx1 = fmaxf(mx1, fmaxf(s[ni][2], s[ni][3]));
    }
    mx0 = fmaxf(mx0, __shfl_xor_sync(0xffffffffu, mx0, 1));
    mx0 = fmaxf(mx0, __shfl_xor_sync(0xffffffffu, mx0, 2));
    mx1 = fmaxf(mx1, __shfl_xor_sync(0xffffffffu, mx1, 1));
    mx1 = fmaxf(mx1, __shfl_xor_sync(0xffffffffu, mx1, 2));

    float sm0 = 0.f, sm1 = 0.f;
#pragma unroll
    for (int ni = 0; ni < 8; ni++) {
        s[ni][0] = __expf(s[ni][0] - mx0); sm0 += s[ni][0];
        s[ni][1] = __expf(s[ni][1] - mx0); sm0 += s[ni][1];
        s[ni][2] = __expf(s[ni][2] - mx1); sm1 += s[ni][2];
        s[ni][3] = __expf(s[ni][3] - mx1); sm1 += s[ni][3];
    }
    sm0 += __shfl_xor_sync(0xffffffffu, sm0, 1);
    sm0 += __shfl_xor_sync(0xffffffffu, sm0, 2);
    sm1 += __shfl_xor_sync(0xffffffffu, sm1, 1);
    sm1 += __shfl_xor_sync(0xffffffffu, sm1, 2);
    float inv0 = 1.f / sm0, inv1 = 1.f / sm1;

#pragma unroll
    for (int ni = 0; ni < 8; ni++) {
        int c0 = ni * 8 + 2 * t4;
        Qs[rA * 68 + c0]     = f2tf32(s[ni][0] * inv0);
        Qs[rA * 68 + c0 + 1] = f2tf32(s[ni][1] * inv0);
        Qs[rB * 68 + c0]     = f2tf32(s[ni][2] * inv1);
        Qs[rB * 68 + c0 + 1] = f2tf32(s[ni][3] * inv1);
    }
    // V^T -> Ks
#pragma unroll
    for (int i = tid * 4; i < TT * HDIM; i += 512) {
        int t = i >> 6, d = i & 63;
        uint4 v4 = *(const uint4*)(gv + base + i);
        Ks[(d + 0) * 68 + t] = v4.x;
        Ks[(d + 1) * 68 + t] = v4.y;
        Ks[(d + 2) * 68 + t] = v4.z;
        Ks[(d + 3) * 68 + t] = v4.w;
    }
    __syncthreads();

    float o[8][4];
#pragma unroll
    for (int ni = 0; ni < 8; ni++)
#pragma unroll
        for (int j = 0; j < 4; j++) o[ni][j] = 0.f;

#pragma unroll
    for (int ks = 0; ks < 64; ks += 8) {
        uint32_t af[4];
        int r = rbase + g;
        af[0] = Qs[r * 68 + ks + t4];
        af[1] = Qs[(r + 8) * 68 + ks + t4];
        af[2] = Qs[r * 68 + ks + t4 + 4];
        af[3] = Qs[(r + 8) * 68 + ks + t4 + 4];
#pragma unroll
        for (int ni = 0; ni < 8; ni++) {
            uint32_t bf[2];
            bf[0] = Ks[(ni * 8 + g) * 68 + ks + t4];
            bf[1] = Ks[(ni * 8 + g) * 68 + ks + t4 + 4];
            mma_tf32(o[ni], af, bf);
        }
    }
    __syncthreads();    // everyone done reading Ks

    // O^T (tf32) -> Ks[dd][t]
#pragma unroll
    for (int ni = 0; ni < 8; ni++) {
        int dd = ni * 8 + 2 * t4;
        Ks[(dd + 0) * 68 + rA] = f2tf32(o[ni][0]);
        Ks[(dd + 1) * 68 + rA] = f2tf32(o[ni][1]);
        Ks[(dd + 0) * 68 + rB] = f2tf32(o[ni][2]);
        Ks[(dd + 1) * 68 + rB] = f2tf32(o[ni][3]);
    }
    __syncthreads();

    // Dump to g_o2[c][token-sigma], coalesced 16B chunks.
    const int bn = bh >> 3, h = bh & 7;
    uint32_t* go2 = (uint32_t*)g_o2;
    const int chunk = tid & 15;
    const int hi = (chunk >> 3) * 32, m8 = chunk & 7;
#pragma unroll
    for (int p = 0; p < 8; p++) {
        int row = (tid >> 4) + p * 8;     // channel-within-head 0..63
        uint4 w;
        w.x = Ks[row * 68 + hi + m8];
        w.y = Ks[row * 68 + hi + m8 + 8];
        w.z = Ks[row * 68 + hi + m8 + 16];
        w.w = Ks[row * 68 + hi + m8 + 24];
        *(uint4*)(go2 + (size_t)(h * 64 + row) * TOKENS + bn * 64 + chunk * 4) = w;
    }
}

// ---------------------------------------------------------------------------
// Kernel 3: output projection + bias + ReLU. grid (4, 1360): x = n-block.
// ---------------------------------------------------------------------------
__global__ __launch_bounds__(256, 2)
void out_kernel(const float* __restrict__ bo, float* __restrict__ out)
{
    extern __shared__ float sm[];
    __shared__ int outOff[128];

    const int tid = threadIdx.x;
    const int m0  = blockIdx.y * 128;
    const int r0  = blockIdx.x * 128;

    if (tid < 128) {
        int token = m0 + tid;
        int bn = token >> 6;
        int b = bn / NPOS, n = bn % NPOS;
        outOff[tid] = (b * COUT * NPOS + n) * TT + (token & 63);
    }

    int kA[4], dstA[4], gB[4], dstB[4];
#pragma unroll
    for (int j = 0; j < 4; j++) {
        int cidx = tid + j * 256;
        kA[j] = cidx >> 5;
        int tc = cidx & 31;
        dstA[j] = kA[j] * SA + tc * 4;
        kA[j] = kA[j] * TOKENS + m0 + tc * 4;       // fold into single offset
        int nn = cidx >> 3, kc = cidx & 7;
        gB[j]   = ((3 * 512 + r0 + nn) * 16) * 32 + kc * 4;
        dstB[j] = nn * SB + kc * 4;
    }

    const int lane = tid & 31, wid = tid >> 5;
    const int wm = wid & 3, wn = wid >> 2;
    const int g = lane >> 2, t4 = lane & 3;
    const int mbase = wm * 32, nbase = wn * 64;

    float acc[2][8][4];
#pragma unroll
    for (int mi = 0; mi < 2; mi++)
#pragma unroll
        for (int ni = 0; ni < 8; ni++)
#pragma unroll
            for (int j = 0; j < 4; j++) acc[mi][ni][j] = 0.f;

    auto issue = [&](int stage, int kt) {
        float* As = sm + stage * STAGE;
        float* Bs = As + AW;
#pragma unroll
        for (int j = 0; j < 4; j++)
            cpasync16(As + dstA[j], g_o2 + kA[j] + kt * 32 * TOKENS);
#pragma unroll
        for (int j = 0; j < 4; j++)
            cpasync16(Bs + dstB[j], g_w + gB[j] + kt * 32);
    };

#pragma unroll
    for (int s = 0; s < 3; s++) { issue(s, s); CP_COMMIT(); }

    for (int it = 0; it < 16; it++) {
        CP_WAIT2();
        __syncthreads();
        const int buf = it % 3;
        const float* As = sm + buf * STAGE;
        const float* Bs = As + AW;
        mma_ktile(As, Bs, acc, mbase, nbase, g, t4);
        __syncthreads();
        int nx = it + 3;
        if (nx < 16) issue(buf, nx);
        CP_COMMIT();
    }

#pragma unroll
    for (int mi = 0; mi < 2; mi++) {
        int rloc = mbase + mi * 16 + g;
        int off0 = outOff[rloc];
        int off1 = outOff[rloc + 8];
#pragma unroll
        for (int ni = 0; ni < 8; ni++) {
            int jj = nbase + ni * 8 + 2 * t4;
            int o = r0 + jj;
            float b0 = bo[o], b1 = bo[o + 1];
            out[off0 + o * NTSTR]       = fmaxf(acc[mi][ni][0] + b0, 0.f);
            out[off0 + (o + 1) * NTSTR] = fmaxf(acc[mi][ni][1] + b1, 0.f);
            out[off1 + o * NTSTR]       = fmaxf(acc[mi][ni][2] + b0, 0.f);
            out[off1 + (o + 1) * NTSTR] = fmaxf(acc[mi][ni][3] + b1, 0.f);
        }
    }
}

// ---------------------------------------------------------------------------
extern "C" void kernel_launch(void* const* d_in, const int* in_sizes, int n_in,
                              void* d_out, int out_size)
{
    const float* x   = (const float*)d_in[0];
    const float* tem = (const float*)d_in[1];
    const float* Wq  = (const float*)d_in[2];
    const float* bq  = (const float*)d_in[3];
    const float* Wk  = (const float*)d_in[4];
    const float* bk  = (const float*)d_in[5];
    const float* Wv  = (const float*)d_in[6];
    const float* bv  = (const float*)d_in[7];
    const float* Wo  = (const float*)d_in[8];
    const float* bo  = (const float*)d_in[9];
    float* out = (float*)d_out;

    cudaFuncSetAttribute(qkv_kernel, cudaFuncAttributeMaxDynamicSharedMemorySize, SMEM_BYTES);
    cudaFuncSetAttribute(out_kernel, cudaFuncAttributeMaxDynamicSharedMemorySize, SMEM_BYTES);

    cvt_x_kernel<<<512 * 16, 256>>>(x, tem);
    cvt_w_kernel<<<4096, 256>>>(Wq, Wk, Wv, Wo);

    dim3 g1(12, BN / 2);
    qkv_kernel<<<g1, 256, SMEM_BYTES>>>(bq, bk, bv);

    attn_kernel<<<BN * NHEAD, 128>>>();

    dim3 g3(4, BN / 2);
    out_kernel<<<g3, 256, SMEM_BYTES>>>(bo, out);
}

// round 11
// speedup vs baseline: 2.2059x; 1.8006x over previous
#include <cuda_runtime.h>
#include <cuda_fp16.h>
#include <cstdint>

#define BATCH   16
#define CHX     256
#define NPOS    170
#define TT      64
#define NHEAD   8
#define HDIM    64
#define BN      (BATCH*NPOS)      // 2720
#define TOKENS  (BN*TT)           // 174080
#define NTSTR   (NPOS*TT)         // 10880
#define QE      (TOKENS*512)      // 89,128,960

// Device scratch (fp16). g_x/g_o2: [token][c 512]. g_q/g_k: per-(bn,h) [t][dd].
// g_v: per-(bn,h) [dd][t] (pre-transposed for the PV matmul).
__device__ __half g_x[QE];
__device__ __half g_w[4*512*512];   // [mat][n][k] row-major
__device__ __half g_q[QE];
__device__ __half g_k[QE];
__device__ __half g_v[QE];
__device__ __half g_o2[QE];

// ---------------------------------------------------------------------------
__device__ __forceinline__ void mma_f16(float* d, const uint32_t* a, const uint32_t* b) {
    asm volatile(
        "mma.sync.aligned.m16n8k16.row.col.f32.f16.f16.f32 "
        "{%0,%1,%2,%3},{%4,%5,%6,%7},{%8,%9},{%0,%1,%2,%3};\n"
        : "+f"(d[0]), "+f"(d[1]), "+f"(d[2]), "+f"(d[3])
        : "r"(a[0]), "r"(a[1]), "r"(a[2]), "r"(a[3]),
          "r"(b[0]), "r"(b[1]));
}

__device__ __forceinline__ uint32_t packh2(float a, float b) {
    __half2 h = __floats2half2_rn(a, b);
    return *(uint32_t*)&h;
}

__device__ __forceinline__ void cpasync16(__half* smem_dst, const __half* gsrc) {
    uint32_t s = (uint32_t)__cvta_generic_to_shared(smem_dst);
    asm volatile("cp.async.cg.shared.global [%0], [%1], 16;\n"
                 :: "r"(s), "l"(gsrc) : "memory");
}
#define CP_COMMIT() asm volatile("cp.async.commit_group;\n" ::: "memory")
#define CP_WAIT3()  asm volatile("cp.async.wait_group 3;\n" ::: "memory")

// ---------------------------------------------------------------------------
// Prepass 1: x||tem -> g_x fp16 [token][c], via smem transpose (both sides
// coalesced). grid BN, block 256.
// ---------------------------------------------------------------------------
__global__ void cvt_x_kernel(const float* __restrict__ x, const float* __restrict__ tem)
{
    __shared__ float smt[64 * 67];
    const int blk = blockIdx.x;
    const int b = blk / NPOS, n = blk % NPOS;
    const int tid = threadIdx.x;

    for (int chunk = 0; chunk < 8; chunk++) {
        const int c0 = chunk * 64;
        const float* src = (c0 < CHX)
            ? x   + (size_t)(b * CHX + c0) * NTSTR
            : tem + (size_t)(b * CHX + c0 - CHX) * NTSTR;
#pragma unroll
        for (int i = 0; i < 16; i++) {
            int idx = tid + i * 256;
            int cl = idx >> 6, t = idx & 63;
            smt[cl * 67 + t] = __ldg(&src[(size_t)cl * NTSTR + n * TT + t]);
        }
        __syncthreads();
#pragma unroll
        for (int i = 0; i < 16; i++) {
            int idx = tid + i * 256;
            int t = idx >> 6, cl = idx & 63;
            g_x[((size_t)(b * NPOS + n) * TT + t) * 512 + c0 + cl] =
                __float2half_rn(smt[cl * 67 + t]);
        }
        __syncthreads();
    }
}

// ---------------------------------------------------------------------------
// Prepass 2: weights -> g_w fp16 [mat][n][k]. 1M elems, grid 4096 x 256.
// ---------------------------------------------------------------------------
__global__ void cvt_w_kernel(const float* __restrict__ Wq, const float* __restrict__ Wk,
                             const float* __restrict__ Wv, const float* __restrict__ Wo)
{
    int e = blockIdx.x * 256 + threadIdx.x;
    int mat = e >> 18;
    int rem = e & 0x3FFFF;
    const float* W = (mat == 0) ? Wq : (mat == 1) ? Wk : (mat == 2) ? Wv : Wo;
    g_w[e] = __float2half_rn(__ldg(&W[rem]));
}

// ---------------------------------------------------------------------------
// GEMM geometry: Mtile 128 tokens x Ntile 128 x Ktile 32, fp16, f32 accum.
// GEMM smem rows: 40 halfs = 20 words (32 data + 8 pad) -> conflict-free.
// ---------------------------------------------------------------------------
#define SAW     20                 // GEMM tile: words per smem row
#define STAGE_H 10240              // halfs per stage (A 128*40 + B 128*40)
#define NSTAGE  4
#define SMEM_BYTES (NSTAGE*STAGE_H*2)   // 81920

__device__ __forceinline__ void mma_ktile(const uint32_t* As, const uint32_t* Bs,
                                          float (&acc)[2][8][4],
                                          int mbase, int nbase, int g, int t4)
{
#pragma unroll
    for (int ks = 0; ks < 2; ks++) {
        uint32_t a[2][4];
#pragma unroll
        for (int mi = 0; mi < 2; mi++) {
            int r = mbase + mi * 16 + g;
            a[mi][0] = As[r * SAW + 8 * ks + t4];
            a[mi][1] = As[(r + 8) * SAW + 8 * ks + t4];
            a[mi][2] = As[r * SAW + 8 * ks + t4 + 4];
            a[mi][3] = As[(r + 8) * SAW + 8 * ks + t4 + 4];
        }
        uint32_t bv[8][2];
#pragma unroll
        for (int ni = 0; ni < 8; ni++) {
            int c = nbase + ni * 8 + g;
            bv[ni][0] = Bs[c * SAW + 8 * ks + t4];
            bv[ni][1] = Bs[c * SAW + 8 * ks + t4 + 4];
        }
#pragma unroll
        for (int ni = 0; ni < 8; ni++) {
            mma_f16(acc[0][ni], a[0], bv[ni]);
            mma_f16(acc[1][ni], a[1], bv[ni]);
        }
    }
}

// Shared 4-stage cp.async pipeline. aSrc/bSrc: row-major [row][512] fp16.
__device__ __forceinline__ void gemm_pipeline(const __half* aSrc, const __half* bSrc,
                                              __half* sm, float (&acc)[2][8][4],
                                              int tid, int mbase, int nbase,
                                              int g, int t4)
{
    auto issue = [&](int stage, int kt) {
        __half* As = sm + stage * STAGE_H;
        __half* Bs = As + 5120;
#pragma unroll
        for (int j = 0; j < 2; j++) {
            int cidx = tid + j * 256;
            int row = cidx >> 2, part = cidx & 3;
            cpasync16(As + row * 40 + part * 8, aSrc + (size_t)row * 512 + kt * 32 + part * 8);
            cpasync16(Bs + row * 40 + part * 8, bSrc + (size_t)row * 512 + kt * 32 + part * 8);
        }
    };

#pragma unroll
    for (int s = 0; s < NSTAGE; s++) { issue(s, s); CP_COMMIT(); }

    for (int it = 0; it < 16; it++) {
        CP_WAIT3();
        __syncthreads();
        const int buf = it & 3;
        const uint32_t* As = (const uint32_t*)(sm + buf * STAGE_H);
        const uint32_t* Bs = As + 2560;
        mma_ktile(As, Bs, acc, mbase, nbase, g, t4);
        __syncthreads();
        int nx = it + NSTAGE;
        if (nx < 16) issue(buf, nx);
        CP_COMMIT();
    }
}

// ---------------------------------------------------------------------------
// Kernel 1: QKV projection. grid (12, 1360). Epilogue goes through smem for
// fully-coalesced 16B stores; v is written pre-transposed [dd][t].
// ---------------------------------------------------------------------------
__global__ __launch_bounds__(256, 2)
void qkv_kernel(const float* __restrict__ bq, const float* __restrict__ bk,
                const float* __restrict__ bv)
{
    extern __shared__ __half sm[];

    const int tid = threadIdx.x;
    const int bn0 = blockIdx.y * 2;
    const int y   = blockIdx.x;
    const int mat = y >> 2;             // 0:q 1:k 2:v
    const int r0  = (y & 3) * 128;
    const float* bias = (mat == 0) ? bq : (mat == 1) ? bk : bv;

    const int lane = tid & 31, wid = tid >> 5;
    const int wm = wid & 3, wn = wid >> 2;
    const int g = lane >> 2, t4 = lane & 3;
    const int mbase = wm * 32, nbase = wn * 64;

    float acc[2][8][4];
#pragma unroll
    for (int mi = 0; mi < 2; mi++)
#pragma unroll
        for (int ni = 0; ni < 8; ni++)
#pragma unroll
            for (int j = 0; j < 4; j++) acc[mi][ni][j] = 0.f;

    const __half* aSrc = g_x + (size_t)(bn0 * TT) * 512;
    const __half* bSrc = g_w + (size_t)(mat * 512 + r0) * 512;

    gemm_pipeline(aSrc, bSrc, sm, acc, tid, mbase, nbase, g, t4);

    // ---- epilogue: bias, fp16 pack, smem stage (stride 136 halfs / 68 words) ----
    __syncthreads();
    uint32_t* EsW = (uint32_t*)sm;
#pragma unroll
    for (int mi = 0; mi < 2; mi++) {
        int rA = mbase + mi * 16 + g;
#pragma unroll
        for (int ni = 0; ni < 8; ni++) {
            int jj = nbase + ni * 8 + 2 * t4;
            int o = r0 + jj;
            float b0 = __ldg(&bias[o]), b1 = __ldg(&bias[o + 1]);
            EsW[rA * 68 + (jj >> 1)]       = packh2(acc[mi][ni][0] + b0, acc[mi][ni][1] + b1);
            EsW[(rA + 8) * 68 + (jj >> 1)] = packh2(acc[mi][ni][2] + b0, acc[mi][ni][3] + b1);
        }
    }
    __syncthreads();

    if (mat < 2) {
        __half* dst = (mat == 0) ? g_q : g_k;
#pragma unroll
        for (int j = 0; j < 8; j++) {
            int idx = tid + j * 256;
            int trow = idx >> 4, part = idx & 15;
            int o = r0 + part * 8;
            int h = o >> 6, dd = o & 63;
            int bn = bn0 + (trow >> 6), t = trow & 63;
            uint4 val = *(uint4*)&EsW[trow * 68 + part * 4];
            *(uint4*)(dst + (size_t)(bn * NHEAD + h) * 4096 + t * 64 + dd) = val;
        }
    } else {
        // v transposed: g_v[(bn,h)][dd][t]
        const __half* Es = sm;
#pragma unroll
        for (int j = 0; j < 8; j++) {
            int idx = tid + j * 256;
            int ddg = idx & 127;
            int tch = idx >> 7;               // 0..15
            int bnh = tch >> 3, t0 = (tch & 7) * 8;
            int o = r0 + ddg;
            int h = o >> 6, dd = o & 63;
            uint32_t w[4];
#pragma unroll
            for (int p = 0; p < 4; p++) {
                __half lo = Es[(bnh * 64 + t0 + 2 * p) * 136 + ddg];
                __half hi = Es[(bnh * 64 + t0 + 2 * p + 1) * 136 + ddg];
                w[p] = (uint32_t)__half_as_ushort(lo) | ((uint32_t)__half_as_ushort(hi) << 16);
            }
            int bn = bn0 + bnh;
            *(uint4*)(g_v + (size_t)(bn * NHEAD + h) * 4096 + dd * 64 + t0) = *(uint4*)w;
        }
    }
}

// ---------------------------------------------------------------------------
// Kernel 2: causal attention per (bn, head). fp16 operands, f32 softmax.
// Attention smem rows hold 64 halfs -> stride 72 halfs = 36 words (conflict-
// free: 36r mod 32 = 4g+t4 covers all banks).  [R9 bug: reused stride 20]
// ---------------------------------------------------------------------------
#define SATT 36

__global__ __launch_bounds__(128)
void attn_kernel()
{
    __shared__ __half Qs[64 * 72];   // Q -> P -> O
    __shared__ __half Ks[64 * 72];   // K -> V^T
    uint32_t* QsW = (uint32_t*)Qs;
    uint32_t* KsW = (uint32_t*)Ks;

    const int tid = threadIdx.x;
    const int lane = tid & 31, wid = tid >> 5;
    const int g = lane >> 2, t4 = lane & 3;
    const int bh = blockIdx.x;
    const size_t base = (size_t)bh * 4096;

#pragma unroll
    for (int j = 0; j < 4; j++) {
        int idx = tid + j * 128;
        int t = idx >> 3, part = idx & 7;
        *(uint4*)&QsW[t * SATT + part * 4] = *(const uint4*)(g_q + base + t * 64 + part * 8);
        *(uint4*)&KsW[t * SATT + part * 4] = *(const uint4*)(g_k + base + t * 64 + part * 8);
    }
    __syncthreads();

    const int rbase = wid * 16;
    const int rA = rbase + g, rB = rA + 8;

    float s[8][4];
#pragma unroll
    for (int ni = 0; ni < 8; ni++)
#pragma unroll
        for (int j = 0; j < 4; j++) s[ni][j] = 0.f;

#pragma unroll
    for (int ks = 0; ks < 4; ks++) {
        uint32_t a[4];
        a[0] = QsW[rA * SATT + 8 * ks + t4];
        a[1] = QsW[rB * SATT + 8 * ks + t4];
        a[2] = QsW[rA * SATT + 8 * ks + t4 + 4];
        a[3] = QsW[rB * SATT + 8 * ks + t4 + 4];
#pragma unroll
        for (int ni = 0; ni < 8; ni++) {
            uint32_t b[2];
            b[0] = KsW[(ni * 8 + g) * SATT + 8 * ks + t4];
            b[1] = KsW[(ni * 8 + g) * SATT + 8 * ks + t4 + 4];
            mma_f16(s[ni], a, b);
        }
    }

    // mask + softmax (f32, identical math/constants to reference)
    float mx0 = -1e30f, mx1 = -1e30f;
#pragma unroll
    for (int ni = 0; ni < 8; ni++) {
        int c0 = ni * 8 + 2 * t4, c1 = c0 + 1;
        s[ni][0] = (c0 <= rA) ? s[ni][0] * 0.125f : -32767.0f;
        s[ni][1] = (c1 <= rA) ? s[ni][1] * 0.125f : -32767.0f;
        s[ni][2] = (c0 <= rB) ? s[ni][2] * 0.125f : -32767.0f;
        s[ni][3] = (c1 <= rB) ? s[ni][3] * 0.125f : -32767.0f;
        mx0 = fmaxf(mx0, fmaxf(s[ni][0], s[ni][1]));
        mx1 = fmaxf(mx1, fmaxf(s[ni][2], s[ni][3]));
    }
    mx0 = fmaxf(mx0, __shfl_xor_sync(0xffffffffu, mx0, 1));
    mx0 = fmaxf(mx0, __shfl_xor_sync(0xffffffffu, mx0, 2));
    mx1 = fmaxf(mx1, __shfl_xor_sync(0xffffffffu, mx1, 1));
    mx1 = fmaxf(mx1, __shfl_xor_sync(0xffffffffu, mx1, 2));

    float sm0 = 0.f, sm1 = 0.f;
#pragma unroll
    for (int ni = 0; ni < 8; ni++) {
        s[ni][0] = __expf(s[ni][0] - mx0); sm0 += s[ni][0];
        s[ni][1] = __expf(s[ni][1] - mx0); sm0 += s[ni][1];
        s[ni][2] = __expf(s[ni][2] - mx1); sm1 += s[ni][2];
        s[ni][3] = __expf(s[ni][3] - mx1); sm1 += s[ni][3];
    }
    sm0 += __shfl_xor_sync(0xffffffffu, sm0, 1);
    sm0 += __shfl_xor_sync(0xffffffffu, sm0, 2);
    sm1 += __shfl_xor_sync(0xffffffffu, sm1, 1);
    sm1 += __shfl_xor_sync(0xffffffffu, sm1, 2);
    float inv0 = 1.f / sm0, inv1 = 1.f / sm1;

    // P (fp16) into own rows of Qs — no cross-warp hazard (A-frags are own rows)
#pragma unroll
    for (int ni = 0; ni < 8; ni++) {
        QsW[rA * SATT + ni * 4 + t4] = packh2(s[ni][0] * inv0, s[ni][1] * inv0);
        QsW[rB * SATT + ni * 4 + t4] = packh2(s[ni][2] * inv1, s[ni][3] * inv1);
    }

    __syncthreads();           // all warps done reading K
    // V^T tile (already [dd][t] in gmem) -> Ks
#pragma unroll
    for (int j = 0; j < 4; j++) {
        int idx = tid + j * 128;
        int dd = idx >> 3, part = idx & 7;
        *(uint4*)&KsW[dd * SATT + part * 4] = *(const uint4*)(g_v + base + dd * 64 + part * 8);
    }
    __syncthreads();

    float o[8][4];
#pragma unroll
    for (int ni = 0; ni < 8; ni++)
#pragma unroll
        for (int j = 0; j < 4; j++) o[ni][j] = 0.f;

#pragma unroll
    for (int ks = 0; ks < 4; ks++) {
        uint32_t a[4];
        a[0] = QsW[rA * SATT + 8 * ks + t4];
        a[1] = QsW[rB * SATT + 8 * ks + t4];
        a[2] = QsW[rA * SATT + 8 * ks + t4 + 4];
        a[3] = QsW[rB * SATT + 8 * ks + t4 + 4];
#pragma unroll
        for (int ni = 0; ni < 8; ni++) {
            uint32_t b[2];
            b[0] = KsW[(ni * 8 + g) * SATT + 8 * ks + t4];
            b[1] = KsW[(ni * 8 + g) * SATT + 8 * ks + t4 + 4];
            mma_f16(o[ni], a, b);
        }
    }
    __syncthreads();           // all warps done reading P rows before overwrite

    // O (fp16) into own rows of Qs, then coalesced dump to g_o2[token][c]
#pragma unroll
    for (int ni = 0; ni < 8; ni++) {
        QsW[rA * SATT + ni * 4 + t4] = packh2(o[ni][0], o[ni][1]);
        QsW[rB * SATT + ni * 4 + t4] = packh2(o[ni][2], o[ni][3]);
    }
    __syncthreads();

    const int bn = bh >> 3, h = bh & 7;
#pragma unroll
    for (int j = 0; j < 4; j++) {
        int idx = tid + j * 128;
        int t = idx >> 3, part = idx & 7;
        uint4 v = *(uint4*)&QsW[t * SATT + part * 4];
        *(uint4*)(g_o2 + ((size_t)bn * 64 + t) * 512 + h * 64 + part * 8) = v;
    }
}

// ---------------------------------------------------------------------------
// Kernel 3: output projection + bias + ReLU. grid (4, 1360).
// ---------------------------------------------------------------------------
__global__ __launch_bounds__(256, 2)
void out_kernel(const float* __restrict__ bo, float* __restrict__ out)
{
    extern __shared__ __half sm[];
    __shared__ int outOff[128];

    const int tid = threadIdx.x;
    const int m0  = blockIdx.y * 128;
    const int r0  = blockIdx.x * 128;

    if (tid < 128) {
        int token = m0 + tid;
        int bn = token >> 6;
        int b = bn / NPOS, n = bn % NPOS;
        outOff[tid] = (b * 512 * NPOS + n) * TT + (token & 63);
    }

    const int lane = tid & 31, wid = tid >> 5;
    const int wm = wid & 3, wn = wid >> 2;
    const int g = lane >> 2, t4 = lane & 3;
    const int mbase = wm * 32, nbase = wn * 64;

    float acc[2][8][4];
#pragma unroll
    for (int mi = 0; mi < 2; mi++)
#pragma unroll
        for (int ni = 0; ni < 8; ni++)
#pragma unroll
            for (int j = 0; j < 4; j++) acc[mi][ni][j] = 0.f;

    const __half* aSrc = g_o2 + (size_t)m0 * 512;
    const __half* bSrc = g_w + (size_t)(3 * 512 + r0) * 512;

    gemm_pipeline(aSrc, bSrc, sm, acc, tid, mbase, nbase, g, t4);

    // epilogue: bias + relu + scatter to [B,512,N,T] (t-contiguous 32B runs)
#pragma unroll
    for (int mi = 0; mi < 2; mi++) {
        int rloc = mbase + mi * 16 + g;
        int off0 = outOff[rloc];
        int off1 = outOff[rloc + 8];
#pragma unroll
        for (int ni = 0; ni < 8; ni++) {
            int jj = nbase + ni * 8 + 2 * t4;
            int o = r0 + jj;
            float b0 = __ldg(&bo[o]), b1 = __ldg(&bo[o + 1]);
            out[off0 + o * NTSTR]       = fmaxf(acc[mi][ni][0] + b0, 0.f);
            out[off0 + (o + 1) * NTSTR] = fmaxf(acc[mi][ni][1] + b1, 0.f);
            out[off1 + o * NTSTR]       = fmaxf(acc[mi][ni][2] + b0, 0.f);
            out[off1 + (o + 1) * NTSTR] = fmaxf(acc[mi][ni][3] + b1, 0.f);
        }
    }
}

// ---------------------------------------------------------------------------
extern "C" void kernel_launch(void* const* d_in, const int* in_sizes, int n_in,
                              void* d_out, int out_size)
{
    const float* x   = (const float*)d_in[0];
    const float* tem = (const float*)d_in[1];
    const float* Wq  = (const float*)d_in[2];
    const float* bq  = (const float*)d_in[3];
    const float* Wk  = (const float*)d_in[4];
    const float* bk  = (const float*)d_in[5];
    const float* Wv  = (const float*)d_in[6];
    const float* bv  = (const float*)d_in[7];
    const float* Wo  = (const float*)d_in[8];
    const float* bo  = (const float*)d_in[9];
    float* out = (float*)d_out;

    cudaFuncSetAttribute(qkv_kernel, cudaFuncAttributeMaxDynamicSharedMemorySize, SMEM_BYTES);
    cudaFuncSetAttribute(out_kernel, cudaFuncAttributeMaxDynamicSharedMemorySize, SMEM_BYTES);

    cvt_x_kernel<<<BN, 256>>>(x, tem);
    cvt_w_kernel<<<4096, 256>>>(Wq, Wk, Wv, Wo);

    dim3 g1(12, BN / 2);
    qkv_kernel<<<g1, 256, SMEM_BYTES>>>(bq, bk, bv);

    attn_kernel<<<BN * NHEAD, 128>>>();

    dim3 g3(4, BN / 2);
    out_kernel<<<g3, 256, SMEM_BYTES>>>(bo, out);
}

// round 12
// speedup vs baseline: 2.5329x; 1.1483x over previous
#include <cuda_runtime.h>
#include <cuda_fp16.h>
#include <cstdint>

#define BATCH   16
#define CHX     256
#define NPOS    170
#define TT      64
#define NHEAD   8
#define HDIM    64
#define BN      (BATCH*NPOS)      // 2720
#define TOKENS  (BN*TT)           // 174080
#define NTSTR   (NPOS*TT)         // 10880
#define QE      (TOKENS*512)      // 89,128,960

// Device scratch (fp16). g_x/g_o2: [token][c 512]. g_q/g_k: per-(bn,h) [t][dd].
// g_v: per-(bn,h) [dd][t] (pre-transposed for the PV matmul).
__device__ __half g_x[QE];
__device__ __half g_w[4*512*512];   // [mat][n][k] row-major
__device__ __half g_q[QE];
__device__ __half g_k[QE];
__device__ __half g_v[QE];
__device__ __half g_o2[QE];

// ---------------------------------------------------------------------------
__device__ __forceinline__ void mma_f16(float* d, const uint32_t* a, const uint32_t* b) {
    asm volatile(
        "mma.sync.aligned.m16n8k16.row.col.f32.f16.f16.f32 "
        "{%0,%1,%2,%3},{%4,%5,%6,%7},{%8,%9},{%0,%1,%2,%3};\n"
        : "+f"(d[0]), "+f"(d[1]), "+f"(d[2]), "+f"(d[3])
        : "r"(a[0]), "r"(a[1]), "r"(a[2]), "r"(a[3]),
          "r"(b[0]), "r"(b[1]));
}

__device__ __forceinline__ void ldsm4(uint32_t* r, uint32_t addr) {
    asm volatile("ldmatrix.sync.aligned.m8n8.x4.shared.b16 {%0,%1,%2,%3}, [%4];"
                 : "=r"(r[0]), "=r"(r[1]), "=r"(r[2]), "=r"(r[3]) : "r"(addr));
}

__device__ __forceinline__ uint32_t packh2(float a, float b) {
    __half2 h = __floats2half2_rn(a, b);
    return *(uint32_t*)&h;
}

__device__ __forceinline__ void cpasync16(__half* smem_dst, const __half* gsrc) {
    uint32_t s = (uint32_t)__cvta_generic_to_shared(smem_dst);
    asm volatile("cp.async.cg.shared.global [%0], [%1], 16;\n"
                 :: "r"(s), "l"(gsrc) : "memory");
}
#define CP_COMMIT() asm volatile("cp.async.commit_group;\n" ::: "memory")
#define CP_WAIT2()  asm volatile("cp.async.wait_group 2;\n" ::: "memory")

// ---------------------------------------------------------------------------
// Prepass 1: x||tem -> g_x fp16 [token][c], via smem transpose.
// ---------------------------------------------------------------------------
__global__ void cvt_x_kernel(const float* __restrict__ x, const float* __restrict__ tem)
{
    __shared__ float smt[64 * 67];
    const int blk = blockIdx.x;
    const int b = blk / NPOS, n = blk % NPOS;
    const int tid = threadIdx.x;

    for (int chunk = 0; chunk < 8; chunk++) {
        const int c0 = chunk * 64;
        const float* src = (c0 < CHX)
            ? x   + (size_t)(b * CHX + c0) * NTSTR
            : tem + (size_t)(b * CHX + c0 - CHX) * NTSTR;
#pragma unroll
        for (int i = 0; i < 16; i++) {
            int idx = tid + i * 256;
            int cl = idx >> 6, t = idx & 63;
            smt[cl * 67 + t] = __ldg(&src[(size_t)cl * NTSTR + n * TT + t]);
        }
        __syncthreads();
#pragma unroll
        for (int i = 0; i < 16; i++) {
            int idx = tid + i * 256;
            int t = idx >> 6, cl = idx & 63;
            g_x[((size_t)(b * NPOS + n) * TT + t) * 512 + c0 + cl] =
                __float2half_rn(smt[cl * 67 + t]);
        }
        __syncthreads();
    }
}

// ---------------------------------------------------------------------------
// Prepass 2: weights -> g_w fp16 [mat][n][k]. 1M elems, grid 4096 x 256.
// ---------------------------------------------------------------------------
__global__ void cvt_w_kernel(const float* __restrict__ Wq, const float* __restrict__ Wk,
                             const float* __restrict__ Wv, const float* __restrict__ Wo)
{
    int e = blockIdx.x * 256 + threadIdx.x;
    int mat = e >> 18;
    int rem = e & 0x3FFFF;
    const float* W = (mat == 0) ? Wq : (mat == 1) ? Wk : (mat == 2) ? Wv : Wo;
    g_w[e] = __float2half_rn(__ldg(&W[rem]));
}

// ---------------------------------------------------------------------------
// GEMM geometry: Mtile 128 x Ntile 128 x Ktile 32, fp16, f32 accum.
// smem rows: 40 halfs = 80 B (32 data + 8 pad) -> LDSM phases conflict-free.
// Pipeline: 4 slots, depth-3 issue-ahead, ONE __syncthreads per iteration.
// Fragments via ldmatrix.x4 (12 LDSM/warp/ktile vs 48 LDS.32 before).
// ---------------------------------------------------------------------------
#define STAGE_H 10240              // halfs per stage (A 128*40 + B 128*40)
#define SMEM_BYTES (4*STAGE_H*2)   // 81920

__device__ __forceinline__ void gemm_pipeline(const __half* aSrc, const __half* bSrc,
                                              __half* sm, float (&acc)[2][8][4],
                                              int tid, int mbase, int nbase,
                                              int g, int t4)
{
    const int lane = tid & 31;
    const uint32_t smBase = (uint32_t)__cvta_generic_to_shared(sm);

    // ldmatrix per-lane byte offsets (within a stage)
    uint32_t aOff[2], bOff[4];
#pragma unroll
    for (int mi = 0; mi < 2; mi++)
        aOff[mi] = (uint32_t)((mbase + mi * 16 + (lane & 15)) * 80 + ((lane >> 4) & 1) * 16);
#pragma unroll
    for (int p = 0; p < 4; p++)
        bOff[p] = (uint32_t)(5120 * 2 +
                  (nbase + p * 16 + ((lane >> 4) & 1) * 8 + (lane & 7)) * 80 +
                  ((lane >> 3) & 1) * 16);

    auto issue = [&](int stage, int kt) {
        __half* As = sm + stage * STAGE_H;
        __half* Bs = As + 5120;
#pragma unroll
        for (int j = 0; j < 2; j++) {
            int cidx = tid + j * 256;
            int row = cidx >> 2, part = cidx & 3;
            cpasync16(As + row * 40 + part * 8, aSrc + (size_t)row * 512 + kt * 32 + part * 8);
            cpasync16(Bs + row * 40 + part * 8, bSrc + (size_t)row * 512 + kt * 32 + part * 8);
        }
    };

#pragma unroll
    for (int s = 0; s < 3; s++) { issue(s, s); CP_COMMIT(); }

    for (int it = 0; it < 16; it++) {
        CP_WAIT2();            // own copies for tile `it` complete
        __syncthreads();       // all threads' waits done; compute it-1 closed
        int nx = it + 3;
        if (nx < 16) issue(nx & 3, nx);   // slot (it-1)&3 — freed by the sync
        CP_COMMIT();

        const uint32_t stageB = smBase + (uint32_t)((it & 3) * STAGE_H * 2);
#pragma unroll
        for (int ks = 0; ks < 2; ks++) {
            uint32_t a[2][4];
            ldsm4(a[0], stageB + aOff[0] + ks * 32);
            ldsm4(a[1], stageB + aOff[1] + ks * 32);
            uint32_t b[4][4];
#pragma unroll
            for (int p = 0; p < 4; p++)
                ldsm4(b[p], stageB + bOff[p] + ks * 32);
#pragma unroll
            for (int p = 0; p < 4; p++) {
                mma_f16(acc[0][2 * p],     a[0], &b[p][0]);
                mma_f16(acc[1][2 * p],     a[1], &b[p][0]);
                mma_f16(acc[0][2 * p + 1], a[0], &b[p][2]);
                mma_f16(acc[1][2 * p + 1], a[1], &b[p][2]);
            }
        }
    }
}

// ---------------------------------------------------------------------------
// Kernel 1: QKV projection. grid (12, 1360). Coalesced smem-staged epilogue;
// v written pre-transposed [dd][t].
// ---------------------------------------------------------------------------
__global__ __launch_bounds__(256, 2)
void qkv_kernel(const float* __restrict__ bq, const float* __restrict__ bk,
                const float* __restrict__ bv)
{
    extern __shared__ __half sm[];

    const int tid = threadIdx.x;
    const int bn0 = blockIdx.y * 2;
    const int y   = blockIdx.x;
    const int mat = y >> 2;             // 0:q 1:k 2:v
    const int r0  = (y & 3) * 128;
    const float* bias = (mat == 0) ? bq : (mat == 1) ? bk : bv;

    const int lane = tid & 31, wid = tid >> 5;
    const int wm = wid & 3, wn = wid >> 2;
    const int g = lane >> 2, t4 = lane & 3;
    const int mbase = wm * 32, nbase = wn * 64;

    float acc[2][8][4];
#pragma unroll
    for (int mi = 0; mi < 2; mi++)
#pragma unroll
        for (int ni = 0; ni < 8; ni++)
#pragma unroll
            for (int j = 0; j < 4; j++) acc[mi][ni][j] = 0.f;

    const __half* aSrc = g_x + (size_t)(bn0 * TT) * 512;
    const __half* bSrc = g_w + (size_t)(mat * 512 + r0) * 512;

    gemm_pipeline(aSrc, bSrc, sm, acc, tid, mbase, nbase, g, t4);

    // ---- epilogue: bias, fp16 pack, smem stage (stride 136 halfs / 68 words) ----
    __syncthreads();
    uint32_t* EsW = (uint32_t*)sm;
#pragma unroll
    for (int mi = 0; mi < 2; mi++) {
        int rA = mbase + mi * 16 + g;
#pragma unroll
        for (int ni = 0; ni < 8; ni++) {
            int jj = nbase + ni * 8 + 2 * t4;
            int o = r0 + jj;
            float b0 = __ldg(&bias[o]), b1 = __ldg(&bias[o + 1]);
            EsW[rA * 68 + (jj >> 1)]       = packh2(acc[mi][ni][0] + b0, acc[mi][ni][1] + b1);
            EsW[(rA + 8) * 68 + (jj >> 1)] = packh2(acc[mi][ni][2] + b0, acc[mi][ni][3] + b1);
        }
    }
    __syncthreads();

    if (mat < 2) {
        __half* dst = (mat == 0) ? g_q : g_k;
#pragma unroll
        for (int j = 0; j < 8; j++) {
            int idx = tid + j * 256;
            int trow = idx >> 4, part = idx & 15;
            int o = r0 + part * 8;
            int h = o >> 6, dd = o & 63;
            int bn = bn0 + (trow >> 6), t = trow & 63;
            uint4 val = *(uint4*)&EsW[trow * 68 + part * 4];
            *(uint4*)(dst + (size_t)(bn * NHEAD + h) * 4096 + t * 64 + dd) = val;
        }
    } else {
        // v transposed: g_v[(bn,h)][dd][t]
        const __half* Es = sm;
#pragma unroll
        for (int j = 0; j < 8; j++) {
            int idx = tid + j * 256;
            int ddg = idx & 127;
            int tch = idx >> 7;               // 0..15
            int bnh = tch >> 3, t0 = (tch & 7) * 8;
            int o = r0 + ddg;
            int h = o >> 6, dd = o & 63;
            uint32_t w[4];
#pragma unroll
            for (int p = 0; p < 4; p++) {
                __half lo = Es[(bnh * 64 + t0 + 2 * p) * 136 + ddg];
                __half hi = Es[(bnh * 64 + t0 + 2 * p + 1) * 136 + ddg];
                w[p] = (uint32_t)__half_as_ushort(lo) | ((uint32_t)__half_as_ushort(hi) << 16);
            }
            int bn = bn0 + bnh;
            *(uint4*)(g_v + (size_t)(bn * NHEAD + h) * 4096 + dd * 64 + t0) = *(uint4*)w;
        }
    }
}

// ---------------------------------------------------------------------------
// Kernel 2: causal attention per (bn, head). fp16 operands, f32 softmax.
// Row stride 72 halfs = 36 words (conflict-free). DRAM-bound; unchanged.
// ---------------------------------------------------------------------------
#define SATT 36

__global__ __launch_bounds__(128)
void attn_kernel()
{
    __shared__ __half Qs[64 * 72];   // Q -> P -> O
    __shared__ __half Ks[64 * 72];   // K -> V^T
    uint32_t* QsW = (uint32_t*)Qs;
    uint32_t* KsW = (uint32_t*)Ks;

    const int tid = threadIdx.x;
    const int lane = tid & 31, wid = tid >> 5;
    const int g = lane >> 2, t4 = lane & 3;
    const int bh = blockIdx.x;
    const size_t base = (size_t)bh * 4096;

#pragma unroll
    for (int j = 0; j < 4; j++) {
        int idx = tid + j * 128;
        int t = idx >> 3, part = idx & 7;
        *(uint4*)&QsW[t * SATT + part * 4] = *(const uint4*)(g_q + base + t * 64 + part * 8);
        *(uint4*)&KsW[t * SATT + part * 4] = *(const uint4*)(g_k + base + t * 64 + part * 8);
    }
    __syncthreads();

    const int rbase = wid * 16;
    const int rA = rbase + g, rB = rA + 8;

    float s[8][4];
#pragma unroll
    for (int ni = 0; ni < 8; ni++)
#pragma unroll
        for (int j = 0; j < 4; j++) s[ni][j] = 0.f;

#pragma unroll
    for (int ks = 0; ks < 4; ks++) {
        uint32_t a[4];
        a[0] = QsW[rA * SATT + 8 * ks + t4];
        a[1] = QsW[rB * SATT + 8 * ks + t4];
        a[2] = QsW[rA * SATT + 8 * ks + t4 + 4];
        a[3] = QsW[rB * SATT + 8 * ks + t4 + 4];
#pragma unroll
        for (int ni = 0; ni < 8; ni++) {
            uint32_t b[2];
            b[0] = KsW[(ni * 8 + g) * SATT + 8 * ks + t4];
            b[1] = KsW[(ni * 8 + g) * SATT + 8 * ks + t4 + 4];
            mma_f16(s[ni], a, b);
        }
    }

    // mask + softmax (f32, identical math/constants to reference)
    float mx0 = -1e30f, mx1 = -1e30f;
#pragma unroll
    for (int ni = 0; ni < 8; ni++) {
        int c0 = ni * 8 + 2 * t4, c1 = c0 + 1;
        s[ni][0] = (c0 <= rA) ? s[ni][0] * 0.125f : -32767.0f;
        s[ni][1] = (c1 <= rA) ? s[ni][1] * 0.125f : -32767.0f;
        s[ni][2] = (c0 <= rB) ? s[ni][2] * 0.125f : -32767.0f;
        s[ni][3] = (c1 <= rB) ? s[ni][3] * 0.125f : -32767.0f;
        mx0 = fmaxf(mx0, fmaxf(s[ni][0], s[ni][1]));
        mx1 = fmaxf(mx1, fmaxf(s[ni][2], s[ni][3]));
    }
    mx0 = fmaxf(mx0, __shfl_xor_sync(0xffffffffu, mx0, 1));
    mx0 = fmaxf(mx0, __shfl_xor_sync(0xffffffffu, mx0, 2));
    mx1 = fmaxf(mx1, __shfl_xor_sync(0xffffffffu, mx1, 1));
    mx1 = fmaxf(mx1, __shfl_xor_sync(0xffffffffu, mx1, 2));

    float sm0 = 0.f, sm1 = 0.f;
#pragma unroll
    for (int ni = 0; ni < 8; ni++) {
        s[ni][0] = __expf(s[ni][0] - mx0); sm0 += s[ni][0];
        s[ni][1] = __expf(s[ni][1] - mx0); sm0 += s[ni][1];
        s[ni][2] = __expf(s[ni][2] - mx1); sm1 += s[ni][2];
        s[ni][3] = __expf(s[ni][3] - mx1); sm1 += s[ni][3];
    }
    sm0 += __shfl_xor_sync(0xffffffffu, sm0, 1);
    sm0 += __shfl_xor_sync(0xffffffffu, sm0, 2);
    sm1 += __shfl_xor_sync(0xffffffffu, sm1, 1);
    sm1 += __shfl_xor_sync(0xffffffffu, sm1, 2);
    float inv0 = 1.f / sm0, inv1 = 1.f / sm1;

    // P (fp16) into own rows of Qs
#pragma unroll
    for (int ni = 0; ni < 8; ni++) {
        QsW[rA * SATT + ni * 4 + t4] = packh2(s[ni][0] * inv0, s[ni][1] * inv0);
        QsW[rB * SATT + ni * 4 + t4] = packh2(s[ni][2] * inv1, s[ni][3] * inv1);
    }

    __syncthreads();           // all warps done reading K
    // V^T tile (already [dd][t] in gmem) -> Ks
#pragma unroll
    for (int j = 0; j < 4; j++) {
        int idx = tid + j * 128;
        int dd = idx >> 3, part = idx & 7;
        *(uint4*)&KsW[dd * SATT + part * 4] = *(const uint4*)(g_v + base + dd * 64 + part * 8);
    }
    __syncthreads();

    float o[8][4];
#pragma unroll
    for (int ni = 0; ni < 8; ni++)
#pragma unroll
        for (int j = 0; j < 4; j++) o[ni][j] = 0.f;

#pragma unroll
    for (int ks = 0; ks < 4; ks++) {
        uint32_t a[4];
        a[0] = QsW[rA * SATT + 8 * ks + t4];
        a[1] = QsW[rB * SATT + 8 * ks + t4];
        a[2] = QsW[rA * SATT + 8 * ks + t4 + 4];
        a[3] = QsW[rB * SATT + 8 * ks + t4 + 4];
#pragma unroll
        for (int ni = 0; ni < 8; ni++) {
            uint32_t b[2];
            b[0] = KsW[(ni * 8 + g) * SATT + 8 * ks + t4];
            b[1] = KsW[(ni * 8 + g) * SATT + 8 * ks + t4 + 4];
            mma_f16(o[ni], a, b);
        }
    }
    __syncthreads();           // all warps done reading P rows before overwrite

    // O (fp16) into own rows of Qs, then coalesced dump to g_o2[token][c]
#pragma unroll
    for (int ni = 0; ni < 8; ni++) {
        QsW[rA * SATT + ni * 4 + t4] = packh2(o[ni][0], o[ni][1]);
        QsW[rB * SATT + ni * 4 + t4] = packh2(o[ni][2], o[ni][3]);
    }
    __syncthreads();

    const int bn = bh >> 3, h = bh & 7;
#pragma unroll
    for (int j = 0; j < 4; j++) {
        int idx = tid + j * 128;
        int t = idx >> 3, part = idx & 7;
        uint4 v = *(uint4*)&QsW[t * SATT + part * 4];
        *(uint4*)(g_o2 + ((size_t)bn * 64 + t) * 512 + h * 64 + part * 8) = v;
    }
}

// ---------------------------------------------------------------------------
// Kernel 3: output projection + bias + ReLU. grid (4, 1360).
// ---------------------------------------------------------------------------
__global__ __launch_bounds__(256, 2)
void out_kernel(const float* __restrict__ bo, float* __restrict__ out)
{
    extern __shared__ __half sm[];
    __shared__ int outOff[128];

    const int tid = threadIdx.x;
    const int m0  = blockIdx.y * 128;
    const int r0  = blockIdx.x * 128;

    if (tid < 128) {
        int token = m0 + tid;
        int bn = token >> 6;
        int b = bn / NPOS, n = bn % NPOS;
        outOff[tid] = (b * 512 * NPOS + n) * TT + (token & 63);
    }

    const int lane = tid & 31, wid = tid >> 5;
    const int wm = wid & 3, wn = wid >> 2;
    const int g = lane >> 2, t4 = lane & 3;
    const int mbase = wm * 32, nbase = wn * 64;

    float acc[2][8][4];
#pragma unroll
    for (int mi = 0; mi < 2; mi++)
#pragma unroll
        for (int ni = 0; ni < 8; ni++)
#pragma unroll
            for (int j = 0; j < 4; j++) acc[mi][ni][j] = 0.f;

    const __half* aSrc = g_o2 + (size_t)m0 * 512;
    const __half* bSrc = g_w + (size_t)(3 * 512 + r0) * 512;

    gemm_pipeline(aSrc, bSrc, sm, acc, tid, mbase, nbase, g, t4);

    // epilogue: bias + relu + scatter to [B,512,N,T] (t-contiguous 32B runs)
#pragma unroll
    for (int mi = 0; mi < 2; mi++) {
        int rloc = mbase + mi * 16 + g;
        int off0 = outOff[rloc];
        int off1 = outOff[rloc + 8];
#pragma unroll
        for (int ni = 0; ni < 8; ni++) {
            int jj = nbase + ni * 8 + 2 * t4;
            int o = r0 + jj;
            float b0 = __ldg(&bo[o]), b1 = __ldg(&bo[o + 1]);
            out[off0 + o * NTSTR]       = fmaxf(acc[mi][ni][0] + b0, 0.f);
            out[off0 + (o + 1) * NTSTR] = fmaxf(acc[mi][ni][1] + b1, 0.f);
            out[off1 + o * NTSTR]       = fmaxf(acc[mi][ni][2] + b0, 0.f);
            out[off1 + (o + 1) * NTSTR] = fmaxf(acc[mi][ni][3] + b1, 0.f);
        }
    }
}

// ---------------------------------------------------------------------------
extern "C" void kernel_launch(void* const* d_in, const int* in_sizes, int n_in,
                              void* d_out, int out_size)
{
    const float* x   = (const float*)d_in[0];
    const float* tem = (const float*)d_in[1];
    const float* Wq  = (const float*)d_in[2];
    const float* bq  = (const float*)d_in[3];
    const float* Wk  = (const float*)d_in[4];
    const float* bk  = (const float*)d_in[5];
    const float* Wv  = (const float*)d_in[6];
    const float* bv  = (const float*)d_in[7];
    const float* Wo  = (const float*)d_in[8];
    const float* bo  = (const float*)d_in[9];
    float* out = (float*)d_out;

    cudaFuncSetAttribute(qkv_kernel, cudaFuncAttributeMaxDynamicSharedMemorySize, SMEM_BYTES);
    cudaFuncSetAttribute(out_kernel, cudaFuncAttributeMaxDynamicSharedMemorySize, SMEM_BYTES);

    cvt_x_kernel<<<BN, 256>>>(x, tem);
    cvt_w_kernel<<<4096, 256>>>(Wq, Wk, Wv, Wo);

    dim3 g1(12, BN / 2);
    qkv_kernel<<<g1, 256, SMEM_BYTES>>>(bq, bk, bv);

    attn_kernel<<<BN * NHEAD, 128>>>();

    dim3 g3(4, BN / 2);
    out_kernel<<<g3, 256, SMEM_BYTES>>>(bo, out);
}